// round 14
// baseline (speedup 1.0000x reference)
#include <cuda_runtime.h>
#include <cuda_bf16.h>

#define M_SEG 16
#define NTHREADS 256

// Warp-0 computes the 16 affine coefficients (c0,c1) into shared:
//   out = c0[j] + c1[j]*S,   j = floor(S*16) clamped to [0,15]
__device__ __forceinline__ void build_coeffs(float2* sc, const float* __restrict__ u)
{
    int t = threadIdx.x;
    if (t < 32) {
        int lane = t;
        float uu = __ldg(&u[lane & (M_SEG - 1)]);
        float sig = 1.0f / (1.0f + __expf(-uu));
        float a = 0.5f + 4.5f * sig;                 // A_MIN + (A_MAX-A_MIN)*sigmoid
        float seg = (lane < M_SEG) ? a * (1.0f / M_SEG) : 0.0f;

        // inclusive scan over lanes 0..15
        float v = seg;
        #pragma unroll
        for (int off = 1; off < M_SEG; off <<= 1) {
            float nb = __shfl_up_sync(0xffffffffu, v, off);
            if (lane >= off) v += nb;
        }
        float Y = __shfl_sync(0xffffffffu, v, M_SEG - 1);
        float invY = 1.0f / Y;
        if (lane < M_SEG) {
            float excl = v - seg;
            float c1 = a * invY;
            float c0 = (excl - a * (float)lane * (1.0f / M_SEG)) * invY;
            sc[lane] = make_float2(c0, c1);
        }
    }
    __syncthreads();
}

__device__ __forceinline__ float map_one(float s, const float2* sc)
{
    int j = (int)(s * (float)M_SEG);                 // exact: bounds are k/16
    j = min(max(j, 0), M_SEG - 1);
    float2 c = sc[j];
    return fmaf(c.y, s, c.x);
}

// 256-bit global load/store (sm_100+): 8 floats per instruction.
__device__ __forceinline__ void ldg256(const float* p, float* r)
{
    asm volatile("ld.global.v8.f32 {%0,%1,%2,%3,%4,%5,%6,%7}, [%8];"
                 : "=f"(r[0]), "=f"(r[1]), "=f"(r[2]), "=f"(r[3]),
                   "=f"(r[4]), "=f"(r[5]), "=f"(r[6]), "=f"(r[7])
                 : "l"(p));
}

__device__ __forceinline__ void stg256(float* p, const float* r)
{
    asm volatile("st.global.v8.f32 [%0], {%1,%2,%3,%4,%5,%6,%7,%8};"
                 :: "l"(p),
                    "f"(r[0]), "f"(r[1]), "f"(r[2]), "f"(r[3]),
                    "f"(r[4]), "f"(r[5]), "f"(r[6]), "f"(r[7])
                 : "memory");
}

// One-shot: each thread handles 2 x float8 (64B) with grid-wide item stride
// (streams ~32MB apart -> disjoint L2 slices), loads front-batched.
__global__ void __launch_bounds__(NTHREADS) map_kernel(const float* __restrict__ S,
                                                       float* __restrict__ out,
                                                       int n8,
                                                       const float* __restrict__ u)
{
    __shared__ float2 sc[M_SEG];
    build_coeffs(sc, u);

    int stride = gridDim.x * NTHREADS;               // in float8 units
    int i0 = blockIdx.x * NTHREADS + threadIdx.x;
    int i1 = i0 + stride;

    bool p0 = i0 < n8;
    bool p1 = i1 < n8;

    float v0[8], v1[8];
    if (p0) ldg256(S + (size_t)i0 * 8, v0);
    if (p1) ldg256(S + (size_t)i1 * 8, v1);

    if (p0) {
        float r[8];
        #pragma unroll
        for (int k = 0; k < 8; ++k) r[k] = map_one(v0[k], sc);
        stg256(out + (size_t)i0 * 8, r);
    }
    if (p1) {
        float r[8];
        #pragma unroll
        for (int k = 0; k < 8; ++k) r[k] = map_one(v1[k], sc);
        stg256(out + (size_t)i1 * 8, r);
    }
}

// Scalar tail (only launched when n % 8 != 0)
__global__ void __launch_bounds__(256) map_tail_kernel(const float* __restrict__ S,
                                                       float* __restrict__ out,
                                                       int start, int n,
                                                       const float* __restrict__ u)
{
    __shared__ float2 sc[M_SEG];
    build_coeffs(sc, u);
    int i = start + blockIdx.x * blockDim.x + threadIdx.x;
    if (i < n) out[i] = map_one(S[i], sc);
}

extern "C" void kernel_launch(void* const* d_in, const int* in_sizes, int n_in,
                              void* d_out, int out_size)
{
    const float* S = (const float*)d_in[0];
    const float* u = (const float*)d_in[1];
    float* out = (float*)d_out;

    int n = in_sizes[0];
    int n8 = n / 8;

    if (n8 > 0) {
        const int per_block = NTHREADS * 2;          // 2 float8 per thread
        int blocks = (n8 + per_block - 1) / per_block;
        map_kernel<<<blocks, NTHREADS>>>(S, out, n8, u);
    }
    int tail = n - n8 * 8;
    if (tail > 0) {
        map_tail_kernel<<<1, 256>>>(S, out, n8 * 8, n, u);
    }
}

// round 15
// speedup vs baseline: 1.0551x; 1.0551x over previous
#include <cuda_runtime.h>
#include <cuda_bf16.h>

#define M_SEG 16
#define NTHREADS 256

// Warp-0 computes the 16 affine coefficients (c0,c1) into shared:
//   out = c0[j] + c1[j]*S,   j = floor(S*16) clamped to [0,15]
__device__ __forceinline__ void build_coeffs(float2* sc, const float* __restrict__ u)
{
    int t = threadIdx.x;
    if (t < 32) {
        int lane = t;
        float uu = __ldg(&u[lane & (M_SEG - 1)]);
        float sig = 1.0f / (1.0f + __expf(-uu));
        float a = 0.5f + 4.5f * sig;                 // A_MIN + (A_MAX-A_MIN)*sigmoid
        float seg = (lane < M_SEG) ? a * (1.0f / M_SEG) : 0.0f;

        // inclusive scan over lanes 0..15
        float v = seg;
        #pragma unroll
        for (int off = 1; off < M_SEG; off <<= 1) {
            float nb = __shfl_up_sync(0xffffffffu, v, off);
            if (lane >= off) v += nb;
        }
        float Y = __shfl_sync(0xffffffffu, v, M_SEG - 1);
        float invY = 1.0f / Y;
        if (lane < M_SEG) {
            float excl = v - seg;
            float c1 = a * invY;
            float c0 = (excl - a * (float)lane * (1.0f / M_SEG)) * invY;
            sc[lane] = make_float2(c0, c1);
        }
    }
    __syncthreads();
}

__device__ __forceinline__ float map_one(float s, const float2* sc)
{
    int j = (int)(s * (float)M_SEG);                 // exact: bounds are k/16
    j = min(max(j, 0), M_SEG - 1);
    float2 c = sc[j];
    return fmaf(c.y, s, c.x);
}

// 256-bit global load/store (sm_100+): 8 floats per instruction.
__device__ __forceinline__ void ldg256(const float* p, float* r)
{
    asm volatile("ld.global.v8.f32 {%0,%1,%2,%3,%4,%5,%6,%7}, [%8];"
                 : "=f"(r[0]), "=f"(r[1]), "=f"(r[2]), "=f"(r[3]),
                   "=f"(r[4]), "=f"(r[5]), "=f"(r[6]), "=f"(r[7])
                 : "l"(p));
}

__device__ __forceinline__ void stg256(float* p, const float* r)
{
    asm volatile("st.global.v8.f32 [%0], {%1,%2,%3,%4,%5,%6,%7,%8};"
                 :: "l"(p),
                    "f"(r[0]), "f"(r[1]), "f"(r[2]), "f"(r[3]),
                    "f"(r[4]), "f"(r[5]), "f"(r[6]), "f"(r[7])
                 : "memory");
}

// One-shot: 1 x float8 (32B) per thread, full-size grid (matches the grid
// shape that reproducibly gave the best harness totals).
__global__ void __launch_bounds__(NTHREADS) map_kernel(const float* __restrict__ S,
                                                       float* __restrict__ out,
                                                       int n8,
                                                       const float* __restrict__ u)
{
    __shared__ float2 sc[M_SEG];
    build_coeffs(sc, u);

    int i = blockIdx.x * NTHREADS + threadIdx.x;
    if (i < n8) {
        float v[8], r[8];
        ldg256(S + (size_t)i * 8, v);
        #pragma unroll
        for (int k = 0; k < 8; ++k) r[k] = map_one(v[k], sc);
        stg256(out + (size_t)i * 8, r);
    }
}

// Scalar tail (only launched when n % 8 != 0)
__global__ void __launch_bounds__(256) map_tail_kernel(const float* __restrict__ S,
                                                       float* __restrict__ out,
                                                       int start, int n,
                                                       const float* __restrict__ u)
{
    __shared__ float2 sc[M_SEG];
    build_coeffs(sc, u);
    int i = start + blockIdx.x * blockDim.x + threadIdx.x;
    if (i < n) out[i] = map_one(S[i], sc);
}

extern "C" void kernel_launch(void* const* d_in, const int* in_sizes, int n_in,
                              void* d_out, int out_size)
{
    const float* S = (const float*)d_in[0];
    const float* u = (const float*)d_in[1];
    float* out = (float*)d_out;

    int n = in_sizes[0];
    int n8 = n / 8;

    if (n8 > 0) {
        int blocks = (n8 + NTHREADS - 1) / NTHREADS;
        map_kernel<<<blocks, NTHREADS>>>(S, out, n8, u);
    }
    int tail = n - n8 * 8;
    if (tail > 0) {
        map_tail_kernel<<<1, 256>>>(S, out, n8 * 8, n, u);
    }
}